// round 2
// baseline (speedup 1.0000x reference)
#include <cuda_runtime.h>

// GCN fused layer:
//   support = y @ W                      (GEMM1, M=8192, N=1024, K=1024)
//   out     = relu(adj @ support / adj_sumrow + b + x)   (GEMM2 batched, 8x [1024x1024x1024])
//
// Inputs (metadata order): x[8,1024,1024] f32, y[8,1024,1024] f32,
//   adj[8,1024,1024] f32, adj_sumrow[8,1024,1] f32, W[1024,1024] f32, b[1024] f32
// Output: [8,1024,1024] f32

#define BM 128
#define BN 128
#define BK 8
#define TM 8
#define TN 8

// Scratch for the intermediate 'support' tensor (8*1024*1024 f32 = 32 MB).
__device__ float g_support[8u * 1024u * 1024u];

__global__ __launch_bounds__(256, 2) void gcn_sgemm_kernel(
    const float* __restrict__ A,   // [M, K] (per batch via strideA)
    const float* __restrict__ B,   // [K, N] (per batch via strideB)
    float* __restrict__ C,         // [M, N] (per batch via strideC)
    int M, int Ncols, int K,
    long strideA, long strideB, long strideC,
    const float* __restrict__ sumrow,  // [batches, M] (epilogue only)
    const float* __restrict__ bias,    // [Ncols]      (epilogue only)
    const float* __restrict__ xres,    // [batches, M, Ncols] residual (epilogue only)
    int do_epi)
{
    __shared__ float As[BK][BM];
    __shared__ float Bs[BK][BN];

    const int bx = blockIdx.x;
    const int by = blockIdx.y;
    const int bz = blockIdx.z;

    A += (long)bz * strideA + (long)by * BM * K;
    B += (long)bz * strideB;
    C += (long)bz * strideC;

    const int tid = threadIdx.x;
    const int tr = tid / 16;  // 0..15 -> thread row group
    const int tc = tid % 16;  // 0..15 -> thread col group

    // A tile loads: 128 rows x 8 cols; one float4 along K per thread
    const int aRow = tid / 2;            // 0..127
    const int aCol = (tid % 2) * 4;      // 0 or 4
    // B tile loads: 8 rows x 128 cols; one float4 along N per thread
    const int bRow = tid / 32;           // 0..7
    const int bCol = (tid % 32) * 4;     // 0..124

    float acc[TM][TN];
    #pragma unroll
    for (int i = 0; i < TM; i++)
        #pragma unroll
        for (int j = 0; j < TN; j++)
            acc[i][j] = 0.0f;

    const float* Aload = A + (long)aRow * K + aCol;
    const float* Bload = B + (long)bRow * Ncols + (long)bx * BN + bCol;

    for (int k0 = 0; k0 < K; k0 += BK) {
        // Stage A tile (transposed: As[k][m]) and B tile (Bs[k][n])
        float4 a4 = *reinterpret_cast<const float4*>(Aload + k0);
        As[aCol + 0][aRow] = a4.x;
        As[aCol + 1][aRow] = a4.y;
        As[aCol + 2][aRow] = a4.z;
        As[aCol + 3][aRow] = a4.w;

        float4 b4 = *reinterpret_cast<const float4*>(Bload + (long)k0 * Ncols);
        *reinterpret_cast<float4*>(&Bs[bRow][bCol]) = b4;

        __syncthreads();

        #pragma unroll
        for (int k = 0; k < BK; k++) {
            float ra[TM], rb[TN];
            #pragma unroll
            for (int i = 0; i < TM; i += 4) {
                float4 v = *reinterpret_cast<const float4*>(&As[k][tr * TM + i]);
                ra[i + 0] = v.x; ra[i + 1] = v.y; ra[i + 2] = v.z; ra[i + 3] = v.w;
            }
            #pragma unroll
            for (int j = 0; j < TN; j += 4) {
                float4 v = *reinterpret_cast<const float4*>(&Bs[k][tc * TN + j]);
                rb[j + 0] = v.x; rb[j + 1] = v.y; rb[j + 2] = v.z; rb[j + 3] = v.w;
            }
            #pragma unroll
            for (int i = 0; i < TM; i++)
                #pragma unroll
                for (int j = 0; j < TN; j++)
                    acc[i][j] = fmaf(ra[i], rb[j], acc[i][j]);
        }
        __syncthreads();
    }

    const int row0 = by * BM + tr * TM;
    const int col0 = bx * BN + tc * TN;

    if (do_epi) {
        const long xbase = (long)bz * M * Ncols;
        #pragma unroll
        for (int i = 0; i < TM; i++) {
            const int row = row0 + i;
            const float inv = 1.0f / sumrow[(long)bz * M + row];
            const long rbase = xbase + (long)row * Ncols;
            #pragma unroll
            for (int j = 0; j < TN; j += 4) {
                const int col = col0 + j;
                float4 xv = *reinterpret_cast<const float4*>(&xres[rbase + col]);
                float4 bv = *reinterpret_cast<const float4*>(&bias[col]);
                float4 o;
                o.x = fmaxf(acc[i][j + 0] * inv + bv.x + xv.x, 0.0f);
                o.y = fmaxf(acc[i][j + 1] * inv + bv.y + xv.y, 0.0f);
                o.z = fmaxf(acc[i][j + 2] * inv + bv.z + xv.z, 0.0f);
                o.w = fmaxf(acc[i][j + 3] * inv + bv.w + xv.w, 0.0f);
                *reinterpret_cast<float4*>(&C[(long)row * Ncols + col]) = o;
            }
        }
    } else {
        #pragma unroll
        for (int i = 0; i < TM; i++) {
            const int row = row0 + i;
            #pragma unroll
            for (int j = 0; j < TN; j += 4) {
                float4 o;
                o.x = acc[i][j + 0];
                o.y = acc[i][j + 1];
                o.z = acc[i][j + 2];
                o.w = acc[i][j + 3];
                *reinterpret_cast<float4*>(&C[(long)row * Ncols + (col0 + j)]) = o;
            }
        }
    }
}

extern "C" void kernel_launch(void* const* d_in, const int* in_sizes, int n_in,
                              void* d_out, int out_size) {
    const float* x      = (const float*)d_in[0];
    const float* y      = (const float*)d_in[1];
    const float* adj    = (const float*)d_in[2];
    const float* sumrow = (const float*)d_in[3];
    const float* W      = (const float*)d_in[4];
    const float* bias   = (const float*)d_in[5];
    float* out = (float*)d_out;

    float* support = nullptr;
    cudaGetSymbolAddress((void**)&support, g_support);

    dim3 block(256);

    // GEMM1: support[8192,1024] = y[8192,1024] @ W[1024,1024]
    {
        dim3 grid(1024 / BN, 8192 / BM, 1);
        gcn_sgemm_kernel<<<grid, block>>>(
            y, W, support,
            8192, 1024, 1024,
            0, 0, 0,
            nullptr, nullptr, nullptr, 0);
    }

    // GEMM2 (batched, fused epilogue):
    //   out_b = relu(adj_b @ support_b / sumrow_b + bias + x_b)
    {
        dim3 grid(1024 / BN, 1024 / BM, 8);
        const long bstride = 1024L * 1024L;
        gcn_sgemm_kernel<<<grid, block>>>(
            adj, support, out,
            1024, 1024, 1024,
            bstride, bstride, bstride,
            sumrow, bias, x, 1);
    }
}

// round 4
// speedup vs baseline: 5.4481x; 5.4481x over previous
#include <cuda_runtime.h>
#include <cuda_bf16.h>
#include <cstdint>

// ============================================================================
// GCN fused layer via warp-level bf16 mma.sync (portable PTX, no tcgen05 —
// harness ptxas targets .target sm_103 which rejects arch-accelerated instrs):
//   support = y @ W                      (GEMM1, M=8192, N=1024, K=1024, bf16 out)
//   out     = relu(adj @ support / adj_sumrow + b + x)   (GEMM2, 8x 1024^3, f32 out)
// ============================================================================

__device__ __nv_bfloat16 g_ybf [8u * 1024u * 1024u];
__device__ __nv_bfloat16 g_adjbf[8u * 1024u * 1024u];
__device__ __nv_bfloat16 g_wbf [1024u * 1024u];
__device__ __nv_bfloat16 g_sup [8u * 1024u * 1024u];

static __device__ __forceinline__ uint32_t smem_u32(const void* p) {
    uint32_t a;
    asm("{ .reg .u64 t; cvta.to.shared.u64 t, %1; cvt.u32.u64 %0, t; }"
        : "=r"(a) : "l"(p));
    return a;
}

// ---- tile geometry ----------------------------------------------------------
#define BM 128
#define BN 128
#define BK 32
#define LDA_B 80     // A smem row stride bytes (32 bf16 + 8 pad)
#define LDB_B 272    // B smem row stride bytes (128 bf16 + 8 pad)
#define A_SM_BYTES (BM * LDA_B)          // 10240
#define B_SM_BYTES (BK * LDB_B)          // 8704
#define STAGE_BYTES (A_SM_BYTES + B_SM_BYTES)   // 18944
#define BIAS_OFF (2 * STAGE_BYTES)       // 37888
#define SMEM_TOTAL (BIAS_OFF + 512)      // 38400

// ---- PTX wrappers -----------------------------------------------------------
#define CP_ASYNC_16(saddr, gptr) \
    asm volatile("cp.async.cg.shared.global [%0], [%1], 16;" \
        :: "r"(saddr), "l"(gptr) : "memory")
#define CP_ASYNC_COMMIT() asm volatile("cp.async.commit_group;" ::: "memory")
#define CP_ASYNC_WAIT_ALL() asm volatile("cp.async.wait_group 0;" ::: "memory")

#define LDMATRIX_X4(r0, r1, r2, r3, addr) \
    asm volatile("ldmatrix.sync.aligned.m8n8.x4.shared.b16 {%0,%1,%2,%3}, [%4];" \
        : "=r"(r0), "=r"(r1), "=r"(r2), "=r"(r3) : "r"(addr))
#define LDMATRIX_X4_T(r0, r1, r2, r3, addr) \
    asm volatile("ldmatrix.sync.aligned.m8n8.x4.trans.shared.b16 {%0,%1,%2,%3}, [%4];" \
        : "=r"(r0), "=r"(r1), "=r"(r2), "=r"(r3) : "r"(addr))

#define MMA_BF16(c, a0, a1, a2, a3, b0, b1) \
    asm volatile("mma.sync.aligned.m16n8k16.row.col.f32.bf16.bf16.f32 " \
        "{%0,%1,%2,%3}, {%4,%5,%6,%7}, {%8,%9}, {%0,%1,%2,%3};" \
        : "+f"((c)[0]), "+f"((c)[1]), "+f"((c)[2]), "+f"((c)[3]) \
        : "r"(a0), "r"(a1), "r"(a2), "r"(a3), "r"(b0), "r"(b1))

// ---- f32 -> bf16 conversion -------------------------------------------------
__global__ void cvt_f32_bf16(const float4* __restrict__ in,
                             uint2* __restrict__ out, int n4) {
    int i = blockIdx.x * blockDim.x + threadIdx.x;
    if (i >= n4) return;
    float4 v = in[i];
    uint32_t a = (uint32_t)__bfloat16_as_ushort(__float2bfloat16_rn(v.x))
               | ((uint32_t)__bfloat16_as_ushort(__float2bfloat16_rn(v.y)) << 16);
    uint32_t b = (uint32_t)__bfloat16_as_ushort(__float2bfloat16_rn(v.z))
               | ((uint32_t)__bfloat16_as_ushort(__float2bfloat16_rn(v.w)) << 16);
    out[i] = make_uint2(a, b);
}

// ---- mma.sync GEMM kernel ---------------------------------------------------
// A: [M,K] bf16 row-major.  B: [K,N] bf16 row-major.
// 256 threads = 8 warps (2 M x 4 N), warp tile 64x32, mma m16n8k16.
__global__ __launch_bounds__(256, 2)
void gcn_mma_kernel(
    const __nv_bfloat16* __restrict__ A,
    const __nv_bfloat16* __restrict__ B,
    void* __restrict__ Cout,
    int M, int N, int K,
    long strideA, long strideB, long strideC,
    const float* __restrict__ sumrow,
    const float* __restrict__ bias,
    const float* __restrict__ xres,
    int do_epi)
{
    extern __shared__ char smem[];
    const uint32_t sb = smem_u32(smem);
    const int tid = threadIdx.x;
    const int wid = tid >> 5;
    const int lane = tid & 31;
    const int bx = blockIdx.x, by = blockIdx.y, bz = blockIdx.z;

    A += (long)bz * strideA + (long)by * BM * K;
    B += (long)bz * strideB + (long)bx * BN;

    if (do_epi && tid < 128)
        ((float*)(smem + BIAS_OFF))[tid] = bias[bx * BN + tid];

    // ---- stage loader: cp.async 16B chunks ----------------------------------
    // A tile: 128 rows x 4 chunks; B tile: 32 rows x 16 chunks. 2 chunks/thread each.
    const int aRow0 = tid >> 2, aC16 = tid & 3;          // + c*64 rows
    const int bRow0 = tid >> 4, bC16 = tid & 15;         // + c*16 rows
    auto load_stage = [&](int s, int k0) {
        const uint32_t base = sb + s * STAGE_BYTES;
        #pragma unroll
        for (int c = 0; c < 2; c++) {
            const int row = aRow0 + c * 64;
            const __nv_bfloat16* g = A + (long)row * K + k0 + aC16 * 8;
            CP_ASYNC_16(base + row * LDA_B + aC16 * 16, g);
        }
        #pragma unroll
        for (int c = 0; c < 2; c++) {
            const int row = bRow0 + c * 16;
            const __nv_bfloat16* g = B + (long)(k0 + row) * N + bC16 * 8;
            CP_ASYNC_16(base + A_SM_BYTES + row * LDB_B + bC16 * 16, g);
        }
        CP_ASYNC_COMMIT();
    };

    const int wm = wid >> 2;       // 0..1  -> M offset wm*64
    const int wn = wid & 3;        // 0..3  -> N offset wn*32

    float acc[4][4][4];
    #pragma unroll
    for (int i = 0; i < 4; i++)
        #pragma unroll
        for (int j = 0; j < 4; j++)
            #pragma unroll
            for (int k = 0; k < 4; k++)
                acc[i][j][k] = 0.0f;

    // precomputed ldmatrix lane addressing
    const int a_row_in = lane & 15;            // row within 16-row block
    const int a_koff = (lane >> 4) * 16;       // byte offset: 0 or 16 (8 bf16)
    const int b_grp = lane >> 3, b_in = lane & 7;
    const int b_krow_in = (b_grp & 1) * 8 + b_in;   // k row within 16
    const int b_noff = (b_grp >> 1) * 16;           // byte offset: 0 or 16

    const int NIT = K / BK;
    load_stage(0, 0);

    for (int it = 0; it < NIT; ++it) {
        CP_ASYNC_WAIT_ALL();
        __syncthreads();
        if (it + 1 < NIT) load_stage((it + 1) & 1, (it + 1) * BK);

        const uint32_t base_a = sb + (it & 1) * STAGE_BYTES;
        const uint32_t base_b = base_a + A_SM_BYTES;

        #pragma unroll
        for (int kk = 0; kk < 2; kk++) {
            uint32_t af[4][4], bf[2][4];
            #pragma unroll
            for (int mt = 0; mt < 4; mt++) {
                const int row = wm * 64 + mt * 16 + a_row_in;
                const uint32_t ad = base_a + row * LDA_B + kk * 32 + a_koff;
                LDMATRIX_X4(af[mt][0], af[mt][1], af[mt][2], af[mt][3], ad);
            }
            #pragma unroll
            for (int nb = 0; nb < 2; nb++) {
                const int krow = kk * 16 + b_krow_in;
                const uint32_t bd = base_b + krow * LDB_B
                                  + wn * 64 + nb * 32 + b_noff;
                LDMATRIX_X4_T(bf[nb][0], bf[nb][1], bf[nb][2], bf[nb][3], bd);
            }
            #pragma unroll
            for (int mt = 0; mt < 4; mt++) {
                #pragma unroll
                for (int nt = 0; nt < 4; nt++) {
                    MMA_BF16(acc[mt][nt],
                             af[mt][0], af[mt][1], af[mt][2], af[mt][3],
                             bf[nt >> 1][(nt & 1) * 2],
                             bf[nt >> 1][(nt & 1) * 2 + 1]);
                }
            }
        }
        __syncthreads();
    }

    // ---- epilogue -----------------------------------------------------------
    // C fragment: rows (lane>>2) and (lane>>2)+8; cols (lane&3)*2 + {0,1}
    const int r_in = lane >> 2;
    const int c_in = (lane & 3) * 2;

    if (do_epi) {
        const float* bsm = (const float*)(smem + BIAS_OFF);
        #pragma unroll
        for (int mt = 0; mt < 4; mt++) {
            #pragma unroll
            for (int half = 0; half < 2; half++) {
                const int row = by * BM + wm * 64 + mt * 16 + r_in + half * 8;
                const float inv = 1.0f / sumrow[bz * M + row];
                const long rb = (long)bz * strideC + (long)row * N + bx * BN;
                #pragma unroll
                for (int nt = 0; nt < 4; nt++) {
                    const int col = wn * 32 + nt * 8 + c_in;
                    const float a0 = acc[mt][nt][half * 2 + 0];
                    const float a1 = acc[mt][nt][half * 2 + 1];
                    float2 xv = *(const float2*)(xres + rb + col);
                    float2 o;
                    o.x = fmaxf(a0 * inv + bsm[col + 0] + xv.x, 0.0f);
                    o.y = fmaxf(a1 * inv + bsm[col + 1] + xv.y, 0.0f);
                    *(float2*)((float*)Cout + rb + col) = o;
                }
            }
        }
    } else {
        __nv_bfloat16* cp = (__nv_bfloat16*)Cout;
        #pragma unroll
        for (int mt = 0; mt < 4; mt++) {
            #pragma unroll
            for (int half = 0; half < 2; half++) {
                const int row = by * BM + wm * 64 + mt * 16 + r_in + half * 8;
                const long rb = (long)row * N + bx * BN;
                #pragma unroll
                for (int nt = 0; nt < 4; nt++) {
                    const int col = wn * 32 + nt * 8 + c_in;
                    uint32_t lo = __bfloat16_as_ushort(
                        __float2bfloat16_rn(acc[mt][nt][half * 2 + 0]));
                    uint32_t hi = __bfloat16_as_ushort(
                        __float2bfloat16_rn(acc[mt][nt][half * 2 + 1]));
                    *(uint32_t*)(cp + rb + col) = lo | (hi << 16);
                }
            }
        }
    }
}

// ---- host launcher ----------------------------------------------------------
extern "C" void kernel_launch(void* const* d_in, const int* in_sizes, int n_in,
                              void* d_out, int out_size) {
    const float* x      = (const float*)d_in[0];
    const float* y      = (const float*)d_in[1];
    const float* adj    = (const float*)d_in[2];
    const float* sumrow = (const float*)d_in[3];
    const float* W      = (const float*)d_in[4];
    const float* bias   = (const float*)d_in[5];
    float* out = (float*)d_out;

    __nv_bfloat16 *ybf, *adjbf, *wbf, *sup;
    cudaGetSymbolAddress((void**)&ybf,   g_ybf);
    cudaGetSymbolAddress((void**)&adjbf, g_adjbf);
    cudaGetSymbolAddress((void**)&wbf,   g_wbf);
    cudaGetSymbolAddress((void**)&sup,   g_sup);

    cudaFuncSetAttribute(gcn_mma_kernel,
                         cudaFuncAttributeMaxDynamicSharedMemorySize, SMEM_TOTAL);

    // f32 -> bf16 conversions
    {
        const int t = 256;
        const int n4_big = 8 * 1024 * 1024 / 4;
        const int n4_w   = 1024 * 1024 / 4;
        cvt_f32_bf16<<<(n4_big + t - 1) / t, t>>>((const float4*)y,   (uint2*)ybf,   n4_big);
        cvt_f32_bf16<<<(n4_big + t - 1) / t, t>>>((const float4*)adj, (uint2*)adjbf, n4_big);
        cvt_f32_bf16<<<(n4_w   + t - 1) / t, t>>>((const float4*)W,   (uint2*)wbf,   n4_w);
    }

    dim3 blk(256);

    // GEMM1: support[8192,1024] (bf16) = y_bf16 @ W_bf16
    gcn_mma_kernel<<<dim3(1024 / BN, 8192 / BM, 1), blk, SMEM_TOTAL>>>(
        ybf, wbf, sup,
        8192, 1024, 1024,
        0, 0, 0,
        nullptr, nullptr, nullptr, 0);

    // GEMM2 (batched, fused epilogue): out = relu(adj @ support / sumrow + b + x)
    gcn_mma_kernel<<<dim3(1024 / BN, 1024 / BM, 8), blk, SMEM_TOTAL>>>(
        adjbf, sup, out,
        1024, 1024, 1024,
        1024L * 1024, 1024L * 1024, 1024L * 1024,
        sumrow, bias, x, 1);
}

// round 5
// speedup vs baseline: 5.8618x; 1.0759x over previous
#include <cuda_runtime.h>
#include <cuda_bf16.h>
#include <cstdint>

// ============================================================================
// GCN fused layer via warp-level bf16 mma.sync (portable PTX; tcgen05 is
// rejected by the harness's .target sm_103 ptxas pass):
//   support = y @ W                      (GEMM1, 8192x1024x1024, bf16 out)
//   out     = relu(adj @ support / adj_sumrow + b + x)   (GEMM2, 8x 1024^3)
// R5: 3-stage cp.async ring (wait_group 1), 1 sync/iter, fused conversions.
// ============================================================================

__device__ __nv_bfloat16 g_ybf  [8u * 1024u * 1024u];
__device__ __nv_bfloat16 g_adjbf[8u * 1024u * 1024u];
__device__ __nv_bfloat16 g_wbf  [1024u * 1024u];
__device__ __nv_bfloat16 g_sup  [8u * 1024u * 1024u];

static __device__ __forceinline__ uint32_t smem_u32(const void* p) {
    uint32_t a;
    asm("{ .reg .u64 t; cvta.to.shared.u64 t, %1; cvt.u32.u64 %0, t; }"
        : "=r"(a) : "l"(p));
    return a;
}

// ---- tile geometry ----------------------------------------------------------
#define BM 128
#define BN 128
#define BK 32
#define NSTAGE 3
#define LDA_B 80     // A smem row stride bytes (32 bf16 + 8 pad)
#define LDB_B 272    // B smem row stride bytes (128 bf16 + 8 pad)
#define A_SM_BYTES (BM * LDA_B)                   // 10240
#define B_SM_BYTES (BK * LDB_B)                   // 8704
#define STAGE_BYTES (A_SM_BYTES + B_SM_BYTES)     // 18944
#define BIAS_OFF (NSTAGE * STAGE_BYTES)           // 56832
#define SMEM_TOTAL (BIAS_OFF + 512)               // 57344

// ---- PTX wrappers -----------------------------------------------------------
#define CP_ASYNC_16(saddr, gptr) \
    asm volatile("cp.async.cg.shared.global [%0], [%1], 16;" \
        :: "r"(saddr), "l"(gptr) : "memory")
#define CP_ASYNC_COMMIT() asm volatile("cp.async.commit_group;" ::: "memory")
#define CP_ASYNC_WAIT_1() asm volatile("cp.async.wait_group 1;" ::: "memory")
#define CP_ASYNC_WAIT_0() asm volatile("cp.async.wait_group 0;" ::: "memory")

#define LDMATRIX_X4(r0, r1, r2, r3, addr) \
    asm volatile("ldmatrix.sync.aligned.m8n8.x4.shared.b16 {%0,%1,%2,%3}, [%4];" \
        : "=r"(r0), "=r"(r1), "=r"(r2), "=r"(r3) : "r"(addr))
#define LDMATRIX_X4_T(r0, r1, r2, r3, addr) \
    asm volatile("ldmatrix.sync.aligned.m8n8.x4.trans.shared.b16 {%0,%1,%2,%3}, [%4];" \
        : "=r"(r0), "=r"(r1), "=r"(r2), "=r"(r3) : "r"(addr))

#define MMA_BF16(c, a0, a1, a2, a3, b0, b1) \
    asm volatile("mma.sync.aligned.m16n8k16.row.col.f32.bf16.bf16.f32 " \
        "{%0,%1,%2,%3}, {%4,%5,%6,%7}, {%8,%9}, {%0,%1,%2,%3};" \
        : "+f"((c)[0]), "+f"((c)[1]), "+f"((c)[2]), "+f"((c)[3]) \
        : "r"(a0), "r"(a1), "r"(a2), "r"(a3), "r"(b0), "r"(b1))

// ---- fused f32 -> bf16 conversion (y ++ adj ++ W, one launch) ---------------
__global__ void cvt_all_bf16(const float4* __restrict__ y,   uint2* __restrict__ yo, int ny4,
                             const float4* __restrict__ a,   uint2* __restrict__ ao, int na4,
                             const float4* __restrict__ w,   uint2* __restrict__ wo, int nw4) {
    const int total = ny4 + na4 + nw4;
    const int stride = gridDim.x * blockDim.x;
    for (int i = blockIdx.x * blockDim.x + threadIdx.x; i < total; i += stride) {
        const float4* in;
        uint2* out;
        int idx = i;
        if (idx < ny4)                { in = y; out = yo; }
        else if ((idx -= ny4) < na4)  { in = a; out = ao; }
        else                          { idx -= na4; in = w; out = wo; }
        float4 v = in[idx];
        uint32_t lo = (uint32_t)__bfloat16_as_ushort(__float2bfloat16_rn(v.x))
                    | ((uint32_t)__bfloat16_as_ushort(__float2bfloat16_rn(v.y)) << 16);
        uint32_t hi = (uint32_t)__bfloat16_as_ushort(__float2bfloat16_rn(v.z))
                    | ((uint32_t)__bfloat16_as_ushort(__float2bfloat16_rn(v.w)) << 16);
        out[idx] = make_uint2(lo, hi);
    }
}

// ---- mma.sync GEMM kernel ---------------------------------------------------
// A: [M,K] bf16 row-major.  B: [K,N] bf16 row-major.
// 256 threads = 8 warps (2 M x 4 N), warp tile 64x32, mma m16n8k16.
__global__ __launch_bounds__(256, 2)
void gcn_mma_kernel(
    const __nv_bfloat16* __restrict__ A,
    const __nv_bfloat16* __restrict__ B,
    void* __restrict__ Cout,
    int M, int N, int K,
    long strideA, long strideB, long strideC,
    const float* __restrict__ sumrow,
    const float* __restrict__ bias,
    const float* __restrict__ xres,
    int do_epi)
{
    extern __shared__ char smem[];
    const uint32_t sb = smem_u32(smem);
    const int tid = threadIdx.x;
    const int wid = tid >> 5;
    const int lane = tid & 31;
    const int bx = blockIdx.x, by = blockIdx.y, bz = blockIdx.z;

    A += (long)bz * strideA + (long)by * BM * K;
    B += (long)bz * strideB + (long)bx * BN;

    if (do_epi && tid < 128)
        ((float*)(smem + BIAS_OFF))[tid] = bias[bx * BN + tid];

    // ---- stage loader: cp.async 16B chunks ----------------------------------
    const int aRow0 = tid >> 2, aC16 = tid & 3;          // A: + c*64 rows
    const int bRow0 = tid >> 4, bC16 = tid & 15;         // B: + c*16 rows
    auto load_stage = [&](int s, int k0) {
        const uint32_t base = sb + s * STAGE_BYTES;
        #pragma unroll
        for (int c = 0; c < 2; c++) {
            const int row = aRow0 + c * 64;
            const __nv_bfloat16* g = A + (long)row * K + k0 + aC16 * 8;
            CP_ASYNC_16(base + row * LDA_B + aC16 * 16, g);
        }
        #pragma unroll
        for (int c = 0; c < 2; c++) {
            const int row = bRow0 + c * 16;
            const __nv_bfloat16* g = B + (long)(k0 + row) * N + bC16 * 8;
            CP_ASYNC_16(base + A_SM_BYTES + row * LDB_B + bC16 * 16, g);
        }
        CP_ASYNC_COMMIT();
    };

    const int wm = wid >> 2;       // 0..1  -> M offset wm*64
    const int wn = wid & 3;        // 0..3  -> N offset wn*32

    float acc[4][4][4];
    #pragma unroll
    for (int i = 0; i < 4; i++)
        #pragma unroll
        for (int j = 0; j < 4; j++)
            #pragma unroll
            for (int k = 0; k < 4; k++)
                acc[i][j][k] = 0.0f;

    // ldmatrix lane addressing
    const int a_row_in = lane & 15;
    const int a_koff = (lane >> 4) * 16;
    const int b_grp = lane >> 3, b_in = lane & 7;
    const int b_krow_in = (b_grp & 1) * 8 + b_in;
    const int b_noff = (b_grp >> 1) * 16;

    const int NIT = K / BK;

    // prime 2 stages
    load_stage(0, 0);
    load_stage(1, BK);

    int cur = 0;                       // stage index of iteration `it` (mod 3)
    for (int it = 0; it < NIT; ++it) {
        if (it + 1 < NIT) CP_ASYNC_WAIT_1(); else CP_ASYNC_WAIT_0();
        __syncthreads();

        // prefetch stage it+2 into ring slot (reuses slot of it-1, already consumed)
        if (it + 2 < NIT) {
            int nxt = cur + 2; if (nxt >= NSTAGE) nxt -= NSTAGE;
            load_stage(nxt, (it + 2) * BK);
        }

        const uint32_t base_a = sb + cur * STAGE_BYTES;
        const uint32_t base_b = base_a + A_SM_BYTES;

        #pragma unroll
        for (int kk = 0; kk < 2; kk++) {
            uint32_t af[4][4], bfr[2][4];
            #pragma unroll
            for (int mt = 0; mt < 4; mt++) {
                const int row = wm * 64 + mt * 16 + a_row_in;
                const uint32_t ad = base_a + row * LDA_B + kk * 32 + a_koff;
                LDMATRIX_X4(af[mt][0], af[mt][1], af[mt][2], af[mt][3], ad);
            }
            #pragma unroll
            for (int nb = 0; nb < 2; nb++) {
                const int krow = kk * 16 + b_krow_in;
                const uint32_t bd = base_b + krow * LDB_B
                                  + wn * 64 + nb * 32 + b_noff;
                LDMATRIX_X4_T(bfr[nb][0], bfr[nb][1], bfr[nb][2], bfr[nb][3], bd);
            }
            #pragma unroll
            for (int mt = 0; mt < 4; mt++) {
                #pragma unroll
                for (int nt = 0; nt < 4; nt++) {
                    MMA_BF16(acc[mt][nt],
                             af[mt][0], af[mt][1], af[mt][2], af[mt][3],
                             bfr[nt >> 1][(nt & 1) * 2],
                             bfr[nt >> 1][(nt & 1) * 2 + 1]);
                }
            }
        }

        if (++cur >= NSTAGE) cur = 0;
    }

    // ---- epilogue -----------------------------------------------------------
    const int r_in = lane >> 2;
    const int c_in = (lane & 3) * 2;

    if (do_epi) {
        const float* bsm = (const float*)(smem + BIAS_OFF);
        #pragma unroll
        for (int mt = 0; mt < 4; mt++) {
            #pragma unroll
            for (int half = 0; half < 2; half++) {
                const int row = by * BM + wm * 64 + mt * 16 + r_in + half * 8;
                const float inv = 1.0f / sumrow[bz * M + row];
                const long rb = (long)bz * strideC + (long)row * N + bx * BN;
                #pragma unroll
                for (int nt = 0; nt < 4; nt++) {
                    const int col = wn * 32 + nt * 8 + c_in;
                    const float a0 = acc[mt][nt][half * 2 + 0];
                    const float a1 = acc[mt][nt][half * 2 + 1];
                    float2 xv = *(const float2*)(xres + rb + col);
                    float2 o;
                    o.x = fmaxf(a0 * inv + bsm[col + 0] + xv.x, 0.0f);
                    o.y = fmaxf(a1 * inv + bsm[col + 1] + xv.y, 0.0f);
                    *(float2*)((float*)Cout + rb + col) = o;
                }
            }
        }
    } else {
        __nv_bfloat16* cp = (__nv_bfloat16*)Cout;
        #pragma unroll
        for (int mt = 0; mt < 4; mt++) {
            #pragma unroll
            for (int half = 0; half < 2; half++) {
                const int row = by * BM + wm * 64 + mt * 16 + r_in + half * 8;
                const long rb = (long)row * N + bx * BN;
                #pragma unroll
                for (int nt = 0; nt < 4; nt++) {
                    const int col = wn * 32 + nt * 8 + c_in;
                    uint32_t lo = __bfloat16_as_ushort(
                        __float2bfloat16_rn(acc[mt][nt][half * 2 + 0]));
                    uint32_t hi = __bfloat16_as_ushort(
                        __float2bfloat16_rn(acc[mt][nt][half * 2 + 1]));
                    *(uint32_t*)(cp + rb + col) = lo | (hi << 16);
                }
            }
        }
    }
}

// ---- host launcher ----------------------------------------------------------
extern "C" void kernel_launch(void* const* d_in, const int* in_sizes, int n_in,
                              void* d_out, int out_size) {
    const float* x      = (const float*)d_in[0];
    const float* y      = (const float*)d_in[1];
    const float* adj    = (const float*)d_in[2];
    const float* sumrow = (const float*)d_in[3];
    const float* W      = (const float*)d_in[4];
    const float* bias   = (const float*)d_in[5];
    float* out = (float*)d_out;

    __nv_bfloat16 *ybf, *adjbf, *wbf, *sup;
    cudaGetSymbolAddress((void**)&ybf,   g_ybf);
    cudaGetSymbolAddress((void**)&adjbf, g_adjbf);
    cudaGetSymbolAddress((void**)&wbf,   g_wbf);
    cudaGetSymbolAddress((void**)&sup,   g_sup);

    cudaFuncSetAttribute(gcn_mma_kernel,
                         cudaFuncAttributeMaxDynamicSharedMemorySize, SMEM_TOTAL);

    // single fused f32 -> bf16 conversion launch (y ++ adj ++ W)
    {
        const int n4_big = 8 * 1024 * 1024 / 4;
        const int n4_w   = 1024 * 1024 / 4;
        cvt_all_bf16<<<2048, 256>>>((const float4*)y,   (uint2*)ybf,   n4_big,
                                    (const float4*)adj, (uint2*)adjbf, n4_big,
                                    (const float4*)W,   (uint2*)wbf,   n4_w);
    }

    dim3 blk(256);

    // GEMM1: support[8192,1024] (bf16) = y_bf16 @ W_bf16
    gcn_mma_kernel<<<dim3(1024 / BN, 8192 / BM, 1), blk, SMEM_TOTAL>>>(
        ybf, wbf, sup,
        8192, 1024, 1024,
        0, 0, 0,
        nullptr, nullptr, nullptr, 0);

    // GEMM2 (batched, fused epilogue): out = relu(adj @ support / sumrow + b + x)
    gcn_mma_kernel<<<dim3(1024 / BN, 1024 / BM, 8), blk, SMEM_TOTAL>>>(
        adjbf, sup, out,
        1024, 1024, 1024,
        1024L * 1024, 1024L * 1024, 1024L * 1024,
        sumrow, bias, x, 1);
}

// round 6
// speedup vs baseline: 6.1920x; 1.0563x over previous
#include <cuda_runtime.h>
#include <cuda_bf16.h>
#include <cstdint>

// ============================================================================
// GCN fused layer via warp-level bf16 mma.sync (portable PTX; tcgen05 is
// rejected by the harness's .target sm_103 ptxas pass):
//   support = y @ W                      (GEMM1, 8192x1024x1024, bf16 out)
//   out     = relu(adj @ support / adj_sumrow + b + x)   (GEMM2, 8x 1024^3)
// R6: BK=64 (half the barriers, 4-phase unrolled body), streaming cvt stores.
// ============================================================================

__device__ __nv_bfloat16 g_ybf  [8u * 1024u * 1024u];
__device__ __nv_bfloat16 g_adjbf[8u * 1024u * 1024u];
__device__ __nv_bfloat16 g_wbf  [1024u * 1024u];
__device__ __nv_bfloat16 g_sup  [8u * 1024u * 1024u];

static __device__ __forceinline__ uint32_t smem_u32(const void* p) {
    uint32_t a;
    asm("{ .reg .u64 t; cvta.to.shared.u64 t, %1; cvt.u32.u64 %0, t; }"
        : "=r"(a) : "l"(p));
    return a;
}

// ---- tile geometry ----------------------------------------------------------
#define BM 128
#define BN 128
#define BK 64
#define NSTAGE 3
#define LDA_B 144    // A smem row stride bytes (64 bf16 = 128B + 16 pad)
#define LDB_B 272    // B smem row stride bytes (128 bf16 + 8 pad)
#define A_SM_BYTES (BM * LDA_B)                   // 18432
#define B_SM_BYTES (BK * LDB_B)                   // 17408
#define STAGE_BYTES (A_SM_BYTES + B_SM_BYTES)     // 35840
#define BIAS_OFF (NSTAGE * STAGE_BYTES)           // 107520
#define SMEM_TOTAL (BIAS_OFF + 512)               // 108032

// ---- PTX wrappers -----------------------------------------------------------
#define CP_ASYNC_16(saddr, gptr) \
    asm volatile("cp.async.cg.shared.global [%0], [%1], 16;" \
        :: "r"(saddr), "l"(gptr) : "memory")
#define CP_ASYNC_COMMIT() asm volatile("cp.async.commit_group;" ::: "memory")
#define CP_ASYNC_WAIT_1() asm volatile("cp.async.wait_group 1;" ::: "memory")
#define CP_ASYNC_WAIT_0() asm volatile("cp.async.wait_group 0;" ::: "memory")

#define LDMATRIX_X4(r0, r1, r2, r3, addr) \
    asm volatile("ldmatrix.sync.aligned.m8n8.x4.shared.b16 {%0,%1,%2,%3}, [%4];" \
        : "=r"(r0), "=r"(r1), "=r"(r2), "=r"(r3) : "r"(addr))
#define LDMATRIX_X4_T(r0, r1, r2, r3, addr) \
    asm volatile("ldmatrix.sync.aligned.m8n8.x4.trans.shared.b16 {%0,%1,%2,%3}, [%4];" \
        : "=r"(r0), "=r"(r1), "=r"(r2), "=r"(r3) : "r"(addr))

#define MMA_BF16(c, a0, a1, a2, a3, b0, b1) \
    asm volatile("mma.sync.aligned.m16n8k16.row.col.f32.bf16.bf16.f32 " \
        "{%0,%1,%2,%3}, {%4,%5,%6,%7}, {%8,%9}, {%0,%1,%2,%3};" \
        : "+f"((c)[0]), "+f"((c)[1]), "+f"((c)[2]), "+f"((c)[3]) \
        : "r"(a0), "r"(a1), "r"(a2), "r"(a3), "r"(b0), "r"(b1))

// ---- fused f32 -> bf16 conversion (y ++ adj ++ W, one launch) ---------------
__global__ void cvt_all_bf16(const float4* __restrict__ y,   uint2* __restrict__ yo, int ny4,
                             const float4* __restrict__ a,   uint2* __restrict__ ao, int na4,
                             const float4* __restrict__ w,   uint2* __restrict__ wo, int nw4) {
    const int total = ny4 + na4 + nw4;
    const int stride = gridDim.x * blockDim.x;
    for (int i = blockIdx.x * blockDim.x + threadIdx.x; i < total; i += stride) {
        const float4* in;
        uint2* out;
        int idx = i;
        if (idx < ny4)                { in = y; out = yo; }
        else if ((idx -= ny4) < na4)  { in = a; out = ao; }
        else                          { idx -= na4; in = w; out = wo; }
        float4 v = __ldcs(in + idx);
        uint32_t lo = (uint32_t)__bfloat16_as_ushort(__float2bfloat16_rn(v.x))
                    | ((uint32_t)__bfloat16_as_ushort(__float2bfloat16_rn(v.y)) << 16);
        uint32_t hi = (uint32_t)__bfloat16_as_ushort(__float2bfloat16_rn(v.z))
                    | ((uint32_t)__bfloat16_as_ushort(__float2bfloat16_rn(v.w)) << 16);
        __stcs(out + idx, make_uint2(lo, hi));
    }
}

// ---- mma.sync GEMM kernel ---------------------------------------------------
// A: [M,K] bf16 row-major.  B: [K,N] bf16 row-major.
// 256 threads = 8 warps (2 M x 4 N), warp tile 64x32, mma m16n8k16, BK=64.
__global__ __launch_bounds__(256, 2)
void gcn_mma_kernel(
    const __nv_bfloat16* __restrict__ A,
    const __nv_bfloat16* __restrict__ B,
    void* __restrict__ Cout,
    int M, int N, int K,
    long strideA, long strideB, long strideC,
    const float* __restrict__ sumrow,
    const float* __restrict__ bias,
    const float* __restrict__ xres,
    int do_epi)
{
    extern __shared__ char smem[];
    const uint32_t sb = smem_u32(smem);
    const int tid = threadIdx.x;
    const int wid = tid >> 5;
    const int lane = tid & 31;
    const int bx = blockIdx.x, by = blockIdx.y, bz = blockIdx.z;

    A += (long)bz * strideA + (long)by * BM * K;
    B += (long)bz * strideB + (long)bx * BN;

    if (do_epi && tid < 128)
        ((float*)(smem + BIAS_OFF))[tid] = bias[bx * BN + tid];

    // ---- stage loader: cp.async 16B chunks ----------------------------------
    // A tile: 128 rows x 8 chunks -> 4/thread.  B tile: 64 rows x 16 chunks -> 4/thread.
    const int aRow0 = tid >> 3, aC16 = tid & 7;          // A: rows += c*32
    const int bRow0 = tid >> 4, bC16 = tid & 15;         // B: rows += c*16
    auto load_stage = [&](int s, int k0) {
        const uint32_t base = sb + s * STAGE_BYTES;
        #pragma unroll
        for (int c = 0; c < 4; c++) {
            const int row = aRow0 + c * 32;
            const __nv_bfloat16* g = A + (long)row * K + k0 + aC16 * 8;
            CP_ASYNC_16(base + row * LDA_B + aC16 * 16, g);
        }
        #pragma unroll
        for (int c = 0; c < 4; c++) {
            const int row = bRow0 + c * 16;
            const __nv_bfloat16* g = B + (long)(k0 + row) * N + bC16 * 8;
            CP_ASYNC_16(base + A_SM_BYTES + row * LDB_B + bC16 * 16, g);
        }
        CP_ASYNC_COMMIT();
    };

    const int wm = wid >> 2;       // 0..1  -> M offset wm*64
    const int wn = wid & 3;        // 0..3  -> N offset wn*32

    float acc[4][4][4];
    #pragma unroll
    for (int i = 0; i < 4; i++)
        #pragma unroll
        for (int j = 0; j < 4; j++)
            #pragma unroll
            for (int k = 0; k < 4; k++)
                acc[i][j][k] = 0.0f;

    // ldmatrix lane addressing
    const int a_row_in = lane & 15;
    const int a_koff = (lane >> 4) * 16;
    const int b_grp = lane >> 3, b_in = lane & 7;
    const int b_krow_in = (b_grp & 1) * 8 + b_in;
    const int b_noff = (b_grp >> 1) * 16;

    const int NIT = K / BK;

    // prime 2 stages of the 3-stage ring
    load_stage(0, 0);
    load_stage(1, BK);

    int cur = 0;
    for (int it = 0; it < NIT; ++it) {
        if (it + 1 < NIT) CP_ASYNC_WAIT_1(); else CP_ASYNC_WAIT_0();
        __syncthreads();

        if (it + 2 < NIT) {
            int nxt = cur + 2; if (nxt >= NSTAGE) nxt -= NSTAGE;
            load_stage(nxt, (it + 2) * BK);
        }

        const uint32_t base_a = sb + cur * STAGE_BYTES;
        const uint32_t base_b = base_a + A_SM_BYTES;

        #pragma unroll
        for (int kk = 0; kk < 4; kk++) {    // 4 x k16 phases per BK=64
            uint32_t af[4][4], bfr[2][4];
            #pragma unroll
            for (int mt = 0; mt < 4; mt++) {
                const int row = wm * 64 + mt * 16 + a_row_in;
                const uint32_t ad = base_a + row * LDA_B + kk * 32 + a_koff;
                LDMATRIX_X4(af[mt][0], af[mt][1], af[mt][2], af[mt][3], ad);
            }
            #pragma unroll
            for (int nb = 0; nb < 2; nb++) {
                const int krow = kk * 16 + b_krow_in;
                const uint32_t bd = base_b + krow * LDB_B
                                  + wn * 64 + nb * 32 + b_noff;
                LDMATRIX_X4_T(bfr[nb][0], bfr[nb][1], bfr[nb][2], bfr[nb][3], bd);
            }
            #pragma unroll
            for (int mt = 0; mt < 4; mt++) {
                #pragma unroll
                for (int nt = 0; nt < 4; nt++) {
                    MMA_BF16(acc[mt][nt],
                             af[mt][0], af[mt][1], af[mt][2], af[mt][3],
                             bfr[nt >> 1][(nt & 1) * 2],
                             bfr[nt >> 1][(nt & 1) * 2 + 1]);
                }
            }
        }

        if (++cur >= NSTAGE) cur = 0;
    }

    // ---- epilogue -----------------------------------------------------------
    const int r_in = lane >> 2;
    const int c_in = (lane & 3) * 2;

    if (do_epi) {
        const float* bsm = (const float*)(smem + BIAS_OFF);
        #pragma unroll
        for (int mt = 0; mt < 4; mt++) {
            #pragma unroll
            for (int half = 0; half < 2; half++) {
                const int row = by * BM + wm * 64 + mt * 16 + r_in + half * 8;
                const float inv = 1.0f / sumrow[bz * M + row];
                const long rb = (long)bz * strideC + (long)row * N + bx * BN;
                #pragma unroll
                for (int nt = 0; nt < 4; nt++) {
                    const int col = wn * 32 + nt * 8 + c_in;
                    const float a0 = acc[mt][nt][half * 2 + 0];
                    const float a1 = acc[mt][nt][half * 2 + 1];
                    float2 xv = *(const float2*)(xres + rb + col);
                    float2 o;
                    o.x = fmaxf(a0 * inv + bsm[col + 0] + xv.x, 0.0f);
                    o.y = fmaxf(a1 * inv + bsm[col + 1] + xv.y, 0.0f);
                    *(float2*)((float*)Cout + rb + col) = o;
                }
            }
        }
    } else {
        __nv_bfloat16* cp = (__nv_bfloat16*)Cout;
        #pragma unroll
        for (int mt = 0; mt < 4; mt++) {
            #pragma unroll
            for (int half = 0; half < 2; half++) {
                const int row = by * BM + wm * 64 + mt * 16 + r_in + half * 8;
                const long rb = (long)row * N + bx * BN;
                #pragma unroll
                for (int nt = 0; nt < 4; nt++) {
                    const int col = wn * 32 + nt * 8 + c_in;
                    uint32_t lo = __bfloat16_as_ushort(
                        __float2bfloat16_rn(acc[mt][nt][half * 2 + 0]));
                    uint32_t hi = __bfloat16_as_ushort(
                        __float2bfloat16_rn(acc[mt][nt][half * 2 + 1]));
                    *(uint32_t*)(cp + rb + col) = lo | (hi << 16);
                }
            }
        }
    }
}

// ---- host launcher ----------------------------------------------------------
extern "C" void kernel_launch(void* const* d_in, const int* in_sizes, int n_in,
                              void* d_out, int out_size) {
    const float* x      = (const float*)d_in[0];
    const float* y      = (const float*)d_in[1];
    const float* adj    = (const float*)d_in[2];
    const float* sumrow = (const float*)d_in[3];
    const float* W      = (const float*)d_in[4];
    const float* bias   = (const float*)d_in[5];
    float* out = (float*)d_out;

    __nv_bfloat16 *ybf, *adjbf, *wbf, *sup;
    cudaGetSymbolAddress((void**)&ybf,   g_ybf);
    cudaGetSymbolAddress((void**)&adjbf, g_adjbf);
    cudaGetSymbolAddress((void**)&wbf,   g_wbf);
    cudaGetSymbolAddress((void**)&sup,   g_sup);

    cudaFuncSetAttribute(gcn_mma_kernel,
                         cudaFuncAttributeMaxDynamicSharedMemorySize, SMEM_TOTAL);

    // single fused f32 -> bf16 conversion launch (y ++ adj ++ W)
    {
        const int n4_big = 8 * 1024 * 1024 / 4;
        const int n4_w   = 1024 * 1024 / 4;
        cvt_all_bf16<<<4096, 256>>>((const float4*)y,   (uint2*)ybf,   n4_big,
                                    (const float4*)adj, (uint2*)adjbf, n4_big,
                                    (const float4*)W,   (uint2*)wbf,   n4_w);
    }

    dim3 blk(256);

    // GEMM1: support[8192,1024] (bf16) = y_bf16 @ W_bf16
    gcn_mma_kernel<<<dim3(1024 / BN, 8192 / BM, 1), blk, SMEM_TOTAL>>>(
        ybf, wbf, sup,
        8192, 1024, 1024,
        0, 0, 0,
        nullptr, nullptr, nullptr, 0);

    // GEMM2 (batched, fused epilogue): out = relu(adj @ support / sumrow + b + x)
    gcn_mma_kernel<<<dim3(1024 / BN, 1024 / BM, 8), blk, SMEM_TOTAL>>>(
        adjbf, sup, out,
        1024, 1024, 1024,
        1024L * 1024, 1024L * 1024, 1024L * 1024,
        sumrow, bias, x, 1);
}